// round 6
// baseline (speedup 1.0000x reference)
#include <cuda_runtime.h>
#include <cstdint>

// Math after collapse (verified, rel_err ~9e-7):
//   attn == 1/H exactly (softmax over an exactly-broadcast head axis)
//   sv[b,j]  = <sum_q v[b,q,:], Wv[j,:]> + Sq*bv[j]
//   row[b,d] = (1/H) * <sv[b,:], Wb[d,:]> + bb[d]
//   out[s,b,d] = row[b,d]  for all s
static constexpr int B  = 4;
static constexpr int SQ = 1024;
static constexpr int SK = 1024;
static constexpr int D  = 1024;
static constexpr int DH = 64;
static constexpr int H  = 16;

static constexpr int QS = 32;            // q-splits
static constexpr int NB = B * QS;        // 128 blocks — one wave on 148 SMs (co-resident)

// Row tile: B*D = 4096 floats = 1024 float4 = 16 KB.
// Output: SK tiles = 1024 tiles = 1,048,576 float4 = 16 MB.
// Each of 128 blocks owns 8 tiles = 8192 float4 = 128 KB.
static constexpr int ROW_F4   = B * D / 4;          // 1024
static constexpr int BLK_F4   = (SK * B * D / 4) / NB;  // 8192
static constexpr int TILES_PB = BLK_F4 / ROW_F4;        // 8

// Scratch (__device__ globals; no allocation allowed)
__device__ float g_partial[QS * B * D];          // 512 KB
__device__ float g_row[B * D];                   // 16 KB
__device__ unsigned long long g_tick[2];         // ticket-barrier counters (never reset)

// L2-coherent vector load (skip non-coherent L1 for cross-block data)
__device__ __forceinline__ float4 ldcg4(const float4* p) {
    float4 r;
    asm volatile("ld.global.cg.v4.f32 {%0,%1,%2,%3}, [%4];"
                 : "=f"(r.x), "=f"(r.y), "=f"(r.z), "=f"(r.w) : "l"(p));
    return r;
}

// Replay-safe grid barrier: monotonic ticket counter, never reset.
// Each launch adds exactly NB arrivals; a block waits until the counter
// reaches the end of its own round ((t/NB+1)*NB). Correct across CUDA-graph
// replays because the counter only grows.
__device__ __forceinline__ void grid_barrier(int idx) {
    __syncthreads();
    if (threadIdx.x == 0) {
        __threadfence();                                   // release
        unsigned long long t = atomicAdd(&g_tick[idx], 1ULL);
        unsigned long long target = (t / NB + 1ULL) * NB;
        while (atomicAdd(&g_tick[idx], 0ULL) < target) __nanosleep(32);
        __threadfence();                                   // acquire
    }
    __syncthreads();
}

// ---------------------------------------------------------------------------
// Single fused kernel: 128 blocks x 1024 threads, all co-resident.
//   phase 1 (all blocks): partial column-sum of v over Sq  -> g_partial
//   phase 2 (blocks 0..3): finish vsum + Wv gemv + Wb gemv -> g_row
//   phase 3 (all blocks): broadcast-store 16 MB output
// ---------------------------------------------------------------------------
__global__ void __launch_bounds__(1024)
fused_kernel(const float* __restrict__ v,
             const float* __restrict__ Wv, const float* __restrict__ bv,
             const float* __restrict__ Wb, const float* __restrict__ bb,
             float4* __restrict__ out4) {
    __shared__ float4 sred[4][256];   // 16 KB
    __shared__ float  s_v[D];         // 4 KB (vsum for phase 2)
    __shared__ float  s_sv[DH];       // 256 B

    const int x = blockIdx.x;
    const int t = threadIdx.x;
    const int t4    = t & 255;        // float4 slot in D (phase 1/2)
    const int strip = t >> 8;         // 0..3

    // ---------------- phase 1: v column-sum ----------------
    {
        const int b  = x & 3;
        const int qs = x >> 2;
        const float4* vb = reinterpret_cast<const float4*>(v + (size_t)b * SQ * D);
        const int q0 = qs * 32 + strip * 8;

        float4 acc = make_float4(0.f, 0.f, 0.f, 0.f);
#pragma unroll
        for (int r = 0; r < 8; ++r) {
            float4 xv = vb[(size_t)(q0 + r) * (D / 4) + t4];
            acc.x += xv.x; acc.y += xv.y; acc.z += xv.z; acc.w += xv.w;
        }
        sred[strip][t4] = acc;
        __syncthreads();
        if (strip == 0) {
            float4 a0 = sred[0][t4], a1 = sred[1][t4], a2 = sred[2][t4], a3 = sred[3][t4];
            float4 s;
            s.x = (a0.x + a1.x) + (a2.x + a3.x);
            s.y = (a0.y + a1.y) + (a2.y + a3.y);
            s.z = (a0.z + a1.z) + (a2.z + a3.z);
            s.w = (a0.w + a1.w) + (a2.w + a3.w);
            reinterpret_cast<float4*>(g_partial)[(size_t)(qs * B + b) * (D / 4) + t4] = s;
        }
    }

    grid_barrier(0);

    // ---------------- phase 2: GEMVs (blocks 0..3 only) ----------------
    if (x < B) {
        const int b = x;
        // finish vsum over QS partials (strip-split over qs)
        float4 acc = make_float4(0.f, 0.f, 0.f, 0.f);
#pragma unroll
        for (int q = strip; q < QS; q += 4) {
            float4 xv = ldcg4(&reinterpret_cast<const float4*>(g_partial)
                                  [(size_t)(q * B + b) * (D / 4) + t4]);
            acc.x += xv.x; acc.y += xv.y; acc.z += xv.z; acc.w += xv.w;
        }
        __syncthreads();          // sred reuse from phase 1
        sred[strip][t4] = acc;
        __syncthreads();
        if (strip == 0) {
            float4 a0 = sred[0][t4], a1 = sred[1][t4], a2 = sred[2][t4], a3 = sred[3][t4];
            float4 s;
            s.x = (a0.x + a1.x) + (a2.x + a3.x);
            s.y = (a0.y + a1.y) + (a2.y + a3.y);
            s.z = (a0.z + a1.z) + (a2.z + a3.z);
            s.w = (a0.w + a1.w) + (a2.w + a3.w);
            reinterpret_cast<float4*>(s_v)[t4] = s;
        }
        __syncthreads();

        // sv[j] = <vsum, Wv[j,:]> + Sq*bv[j]  — 32 warps x 2 j's each
        const int warp = t >> 5, lane = t & 31;
#pragma unroll
        for (int jj = 0; jj < 2; ++jj) {
            const int j = warp * 2 + jj;
            const float* wr = Wv + (size_t)j * D;
            float s = 0.f;
#pragma unroll
            for (int i = 0; i < D / 32; ++i) s += s_v[lane + i * 32] * wr[lane + i * 32];
#pragma unroll
            for (int o = 16; o > 0; o >>= 1) s += __shfl_xor_sync(0xFFFFFFFFu, s, o);
            if (lane == 0) s_sv[j] = s + (float)SQ * bv[j];
        }
        __syncthreads();

        // row[b,d] = (1/H)*<sv, Wb[d,:]> + bb[d]  — one d per thread
        const float4* wb = reinterpret_cast<const float4*>(Wb + (size_t)t * DH);
        float s = 0.f;
#pragma unroll
        for (int j4 = 0; j4 < DH / 4; ++j4) {
            float4 w = wb[j4];
            s += s_sv[j4 * 4 + 0] * w.x + s_sv[j4 * 4 + 1] * w.y
               + s_sv[j4 * 4 + 2] * w.z + s_sv[j4 * 4 + 3] * w.w;
        }
        g_row[b * D + t] = s * (1.0f / (float)H) + bb[t];
    }

    grid_barrier(1);

    // ---------------- phase 3: broadcast-store 16 MB ----------------
    // Thread t holds ONE float4 of the 1024-float4 row tile; block x writes
    // its 8 consecutive tiles. All stores 512B-contiguous per warp.
    {
        const float4 val = ldcg4(&reinterpret_cast<const float4*>(g_row)[t]);
        float4* o = out4 + (size_t)x * BLK_F4;
#pragma unroll
        for (int r = 0; r < TILES_PB; ++r)
            o[r * ROW_F4 + t] = val;
    }
}

extern "C" void kernel_launch(void* const* d_in, const int* in_sizes, int n_in,
                              void* d_out, int out_size) {
    // Inputs: 0=q 1=k 2=h 3=w 4=v 5=Wq 6=bq 7=Wk 8=bk 9=Wv 10=bv 11=Wb 12=bb
    const float* v  = (const float*)d_in[4];
    const float* Wv = (const float*)d_in[9];
    const float* bv = (const float*)d_in[10];
    const float* Wb = (const float*)d_in[11];
    const float* bb = (const float*)d_in[12];

    fused_kernel<<<NB, 1024>>>(v, Wv, bv, Wb, bb, (float4*)d_out);
}

// round 7
// speedup vs baseline: 1.5158x; 1.5158x over previous
#include <cuda_runtime.h>
#include <cstdint>

// Math after collapse (verified, rel_err ~9e-7):
//   attn == 1/H exactly (softmax over an exactly-broadcast head axis)
//   sv[b,j]  = <sum_q v[b,q,:], Wv[j,:]> + Sq*bv[j]
//   row[b,d] = (1/H) * <sv[b,:], Wb[d,:]> + bb[d]
//   out[s,b,d] = row[b,d]  for all s
static constexpr int B  = 4;
static constexpr int SQ = 1024;
static constexpr int SK = 1024;
static constexpr int D  = 1024;
static constexpr int DH = 64;
static constexpr int H  = 16;

static constexpr int QS = 32;             // q-splits
static constexpr int NB = B * QS;         // 128 blocks — single co-resident wave
static constexpr int P2 = 32;             // phase-2 blocks: (b, c) with 8 chunks of 128 d

static constexpr int ROW_F4   = B * D / 4;              // 1024 float4 = 16 KB tile
static constexpr int BLK_F4   = (SK * B * D / 4) / NB;  // 8192 float4 per block
static constexpr int TILES_PB = BLK_F4 / ROW_F4;        // 8

// Scratch (__device__ globals; no allocation allowed)
__device__ float g_partial[QS * B * D];   // 512 KB
__device__ float g_svp[B * 8 * DH];       // 8 KB: per-(b,chunk) partial sv
__device__ float g_row[B * D];            // 16 KB
__device__ unsigned long long g_tick[3];  // monotonic ticket counters (never reset)

__device__ __forceinline__ float4 ldcg4(const float4* p) {
    float4 r;
    asm volatile("ld.global.cg.v4.f32 {%0,%1,%2,%3}, [%4];"
                 : "=f"(r.x), "=f"(r.y), "=f"(r.z), "=f"(r.w) : "l"(p));
    return r;
}
__device__ __forceinline__ float ldcg1(const float* p) {
    float r;
    asm volatile("ld.global.cg.f32 %0, [%1];" : "=f"(r) : "l"(p));
    return r;
}
__device__ __forceinline__ unsigned long long ld_acq(const unsigned long long* p) {
    unsigned long long v;
    asm volatile("ld.global.acquire.gpu.u64 %0, [%1];" : "=l"(v) : "l"(p));
    return v;
}
// Arrive: release all prior writes, bump counter. Returns this block's ticket.
__device__ __forceinline__ unsigned long long arrive(int i) {
    __threadfence();
    return atomicAdd(&g_tick[i], 1ULL);
}
// Wait (thread 0 only) until counter reaches target, then block-sync.
__device__ __forceinline__ void wait_for(int i, unsigned long long target) {
    if (threadIdx.x == 0)
        while (ld_acq(&g_tick[i]) < target) __nanosleep(64);
    __syncthreads();
}

// ---------------------------------------------------------------------------
// One persistent kernel, 128 blocks x 1024 threads (all co-resident).
//  phase 1  (128 blocks): partial column-sum of v            -> g_partial
//  phase 2a ( 32 blocks): vsum chunk + Wv-slice gemv         -> g_svp
//  phase 2b ( 32 blocks): sv = sum chunks; Wb-slice gemv     -> g_row
//  phase 3  (128 blocks): broadcast-store 16 MB
// Sync via monotonic tickets: replay-safe (graph replays serialize, so each
// launch owns a clean window of NB / P2 / P2 tickets per counter).
// ---------------------------------------------------------------------------
__global__ void __launch_bounds__(1024)
fused_kernel(const float* __restrict__ v,
             const float* __restrict__ Wv, const float* __restrict__ bv,
             const float* __restrict__ Wb, const float* __restrict__ bb,
             float4* __restrict__ out4) {
    __shared__ float4 sred[1024];     // 16 KB multi-purpose
    __shared__ float  s_v[128];       // vsum chunk (phase 2a)
    __shared__ float  s_sv[DH];
    __shared__ unsigned long long s_round;

    const int x = blockIdx.x;
    const int t = threadIdx.x;

    // ---------------- phase 1: v column-sum ----------------
    {
        const int b  = x & 3;
        const int qs = x >> 2;
        const int t4    = t & 255;    // float4 slot in D
        const int strip = t >> 8;     // 0..3
        const float4* vb = reinterpret_cast<const float4*>(v + (size_t)b * SQ * D);
        const int q0 = qs * 32 + strip * 8;

        float4 acc = make_float4(0.f, 0.f, 0.f, 0.f);
#pragma unroll
        for (int r = 0; r < 8; ++r) {
            float4 xv = vb[(size_t)(q0 + r) * (D / 4) + t4];
            acc.x += xv.x; acc.y += xv.y; acc.z += xv.z; acc.w += xv.w;
        }
        sred[strip * 256 + t4] = acc;
        __syncthreads();
        if (strip == 0) {
            float4 a0 = sred[t4], a1 = sred[256 + t4], a2 = sred[512 + t4], a3 = sred[768 + t4];
            float4 s;
            s.x = (a0.x + a1.x) + (a2.x + a3.x);
            s.y = (a0.y + a1.y) + (a2.y + a3.y);
            s.z = (a0.z + a1.z) + (a2.z + a3.z);
            s.w = (a0.w + a1.w) + (a2.w + a3.w);
            reinterpret_cast<float4*>(g_partial)[(size_t)(qs * B + b) * (D / 4) + t4] = s;
        }
    }

    // arrive on counter 0; derive this launch's round from the ticket
    __syncthreads();
    if (t == 0) s_round = arrive(0) / NB;
    __syncthreads();
    const unsigned long long round = s_round;

    // ---------------- phase 2 (blocks 0..31) ----------------
    if (x < P2) {
        const int b = x & 3;
        const int c = x >> 2;                 // d-chunk of 128, c in 0..7

        wait_for(0, (round + 1) * NB);        // all partials visible

        // --- 2a: vsum chunk + gemv1 slice ---
        {
            const int slot = t & 31;          // float4 slot in chunk (32)
            const int qs   = t >> 5;          // 0..31
            sred[t] = ldcg4(&reinterpret_cast<const float4*>(g_partial)
                                [(size_t)(qs * B + b) * (D / 4) + c * 32 + slot]);
            __syncthreads();
            if (t < 32) {                     // fixed-order qs reduction
                float4 s = make_float4(0.f, 0.f, 0.f, 0.f);
#pragma unroll
                for (int q = 0; q < 32; ++q) {
                    float4 a = sred[q * 32 + t];
                    s.x += a.x; s.y += a.y; s.z += a.z; s.w += a.w;
                }
                reinterpret_cast<float4*>(s_v)[t] = s;
            }
            __syncthreads();

            // svp[b,c,j] = <vsum_chunk, Wv[j, c*128:+128]> ; 32 warps x 2 j
            const int warp = t >> 5, lane = t & 31;
#pragma unroll
            for (int jj = 0; jj < 2; ++jj) {
                const int j = warp * 2 + jj;
                float4 w = __ldg(&reinterpret_cast<const float4*>(Wv + (size_t)j * D + c * 128)[lane]);
                float4 a = reinterpret_cast<const float4*>(s_v)[lane];
                float s = a.x * w.x + a.y * w.y + a.z * w.z + a.w * w.w;
#pragma unroll
                for (int o = 16; o > 0; o >>= 1) s += __shfl_xor_sync(0xFFFFFFFFu, s, o);
                if (lane == 0) g_svp[(b * 8 + c) * DH + j] = s;
            }
        }
        __syncthreads();
        if (t == 0) arrive(1);

        wait_for(1, (round + 1) * P2);        // all svp chunks visible

        // --- 2b: sv + row slice ---
        if (t < DH) {
            float s = (float)SQ * bv[t];
#pragma unroll
            for (int cc = 0; cc < 8; ++cc) s += ldcg1(&g_svp[(b * 8 + cc) * DH + t]);
            s_sv[t] = s;
        }
        __syncthreads();
        if (t < 128) {
            const int d = c * 128 + t;
            const float4* wb = reinterpret_cast<const float4*>(Wb + (size_t)d * DH);
            float s = 0.f;
#pragma unroll
            for (int j4 = 0; j4 < DH / 4; ++j4) {
                float4 w = __ldg(&wb[j4]);
                s += s_sv[j4 * 4 + 0] * w.x + s_sv[j4 * 4 + 1] * w.y
                   + s_sv[j4 * 4 + 2] * w.z + s_sv[j4 * 4 + 3] * w.w;
            }
            g_row[b * D + d] = s * (1.0f / (float)H) + bb[d];
        }
        __syncthreads();
        if (t == 0) arrive(2);
    }

    // ---------------- phase 3: broadcast-store 16 MB ----------------
    wait_for(2, (round + 1) * P2);            // g_row complete

    {
        const float4 val = ldcg4(&reinterpret_cast<const float4*>(g_row)[t]);
        float4* o = out4 + (size_t)x * BLK_F4;
#pragma unroll
        for (int r = 0; r < TILES_PB; ++r)
            o[r * ROW_F4 + t] = val;
    }
}

extern "C" void kernel_launch(void* const* d_in, const int* in_sizes, int n_in,
                              void* d_out, int out_size) {
    // Inputs: 0=q 1=k 2=h 3=w 4=v 5=Wq 6=bq 7=Wk 8=bk 9=Wv 10=bv 11=Wb 12=bb
    const float* v  = (const float*)d_in[4];
    const float* Wv = (const float*)d_in[9];
    const float* bv = (const float*)d_in[10];
    const float* Wb = (const float*)d_in[11];
    const float* bb = (const float*)d_in[12];

    fused_kernel<<<NB, 1024>>>(v, Wv, bv, Wb, bb, (float4*)d_out);
}